// round 3
// baseline (speedup 1.0000x reference)
#include <cuda_runtime.h>
#include <cuda_bf16.h>
#include <cstdint>

// Problem constants (fixed by the reference)
#define NNODES 100000
#define FDIM   128
#define HID    128
#define NCLS   40
#define EMAX   1600000
#define NEG_SLOPE 0.2f
#define BN_EPS 1e-5f

#define SCAN_BLK 1024
#define NSCANBLK ((NNODES + SCAN_BLK - 1) / SCAN_BLK)   // 98

// ----------------------------------------------------------------------------
// Device scratch (static globals — no runtime allocation allowed)
// ----------------------------------------------------------------------------
__device__ float g_h[NNODES * HID];      // linear output of current layer
__device__ float g_out[NNODES * HID];    // GAT aggregation output / BN input
__device__ float g_bn[NNODES * HID];     // post-BN+ReLU activations
__device__ float g_as[NNODES];
__device__ float g_ad[NNODES];
__device__ float g_stats[2 * HID];       // per-channel sum / sumsq

// CSR (dst -> list of src), rebuilt every launch (deterministic)
__device__ int g_deg[NNODES];
__device__ int g_fill[NNODES];
__device__ int g_rowptr[NNODES + 1];
__device__ int g_blocksum[128];
__device__ int g_csrc[EMAX];

// ----------------------------------------------------------------------------
__device__ __forceinline__ float lrelu(float x) {
    return x > 0.f ? x : NEG_SLOPE * x;
}

// ----------------------------------------------------------------------------
// SGEMM: C[M,NC] = A[M,K] @ B[K,NC] (+ bias per col).  Register-tiled.
// ----------------------------------------------------------------------------
template<int BM, int BN, int BK, int TM, int TN, bool BIAS>
__global__ void sgemm_kernel(const float* __restrict__ A, const float* __restrict__ B,
                             const float* __restrict__ bias, float* __restrict__ C,
                             int M, int K, int NC)
{
    constexpr int THREADS = (BM / TM) * (BN / TN);
    __shared__ float As[BK][BM + 1];
    __shared__ float Bs[BK][BN];

    const int t  = threadIdx.x;
    const int rg = t / (BN / TN);           // row group
    const int cg = t % (BN / TN);           // col group
    const int rowBase = blockIdx.x * BM;

    float acc[TM][TN];
#pragma unroll
    for (int i = 0; i < TM; i++)
#pragma unroll
        for (int j = 0; j < TN; j++) acc[i][j] = 0.f;

    for (int k0 = 0; k0 < K; k0 += BK) {
        for (int i = t; i < BM * BK; i += THREADS) {
            int m = i / BK, k = i % BK;
            int gr = rowBase + m;
            As[k][m] = (gr < M) ? A[(size_t)gr * K + k0 + k] : 0.f;
        }
        for (int i = t; i < BK * BN; i += THREADS) {
            int k = i / BN, n = i % BN;
            Bs[k][n] = (n < NC) ? B[(size_t)(k0 + k) * NC + n] : 0.f;
        }
        __syncthreads();

#pragma unroll
        for (int k = 0; k < BK; k++) {
            float a[TM], b[TN];
#pragma unroll
            for (int i = 0; i < TM; i++) a[i] = As[k][rg * TM + i];
#pragma unroll
            for (int j = 0; j < TN; j++) b[j] = Bs[k][cg * TN + j];
#pragma unroll
            for (int i = 0; i < TM; i++)
#pragma unroll
                for (int j = 0; j < TN; j++) acc[i][j] = fmaf(a[i], b[j], acc[i][j]);
        }
        __syncthreads();
    }

#pragma unroll
    for (int i = 0; i < TM; i++) {
        int row = rowBase + rg * TM + i;
        if (row >= M) continue;
#pragma unroll
        for (int j = 0; j < TN; j++) {
            int col = cg * TN + j;
            if (col < NC) {
                float v = acc[i][j];
                if (BIAS) v += bias[col];
                C[(size_t)row * NC + col] = v;
            }
        }
    }
}

// ----------------------------------------------------------------------------
// CSR build kernels (edge indices are int32 — JAX x64 is disabled by default)
// ----------------------------------------------------------------------------
__global__ void csr_zero_kernel()
{
    int i = blockIdx.x * blockDim.x + threadIdx.x;
    if (i < NNODES) { g_deg[i] = 0; g_fill[i] = 0; }
}

__global__ void csr_count_kernel(const int* __restrict__ dstp, int E)
{
    int e = blockIdx.x * blockDim.x + threadIdx.x;
    if (e < E) atomicAdd(&g_deg[dstp[e]], 1);
}

__global__ void csr_scan_block_kernel()
{
    __shared__ int s[SCAN_BLK];
    int t = threadIdx.x;
    int i = blockIdx.x * SCAN_BLK + t;
    int v = (i < NNODES) ? g_deg[i] : 0;
    s[t] = v;
    __syncthreads();
#pragma unroll
    for (int off = 1; off < SCAN_BLK; off <<= 1) {
        int x = (t >= off) ? s[t - off] : 0;
        __syncthreads();
        s[t] += x;
        __syncthreads();
    }
    if (i < NNODES) g_rowptr[i] = s[t] - v;       // exclusive within block
    if (t == SCAN_BLK - 1) g_blocksum[blockIdx.x] = s[t];
}

__global__ void csr_scan_tops_kernel(int nblocks, int E)
{
    __shared__ int s[128];
    int t = threadIdx.x;                            // 128 threads
    int v = (t < nblocks) ? g_blocksum[t] : 0;
    s[t] = v;
    __syncthreads();
#pragma unroll
    for (int off = 1; off < 128; off <<= 1) {
        int x = (t >= off) ? s[t - off] : 0;
        __syncthreads();
        s[t] += x;
        __syncthreads();
    }
    g_blocksum[t] = s[t] - v;                       // exclusive block offsets
    if (t == 0) g_rowptr[NNODES] = E;
}

__global__ void csr_addoff_kernel()
{
    int i = blockIdx.x * SCAN_BLK + threadIdx.x;
    if (i < NNODES) g_rowptr[i] += g_blocksum[blockIdx.x];
}

__global__ void csr_fill_kernel(const int* __restrict__ srcp,
                                const int* __restrict__ dstp, int E)
{
    int e = blockIdx.x * blockDim.x + threadIdx.x;
    if (e >= E) return;
    int d = dstp[e];
    int p = atomicAdd(&g_fill[d], 1);
    g_csrc[g_rowptr[d] + p] = srcp[e];
}

// ----------------------------------------------------------------------------
// Per-node attention dots (warp per node) + zero BN stats
// ----------------------------------------------------------------------------
__global__ void alphadot_kernel(const float* __restrict__ h,
                                const float* __restrict__ a_s,
                                const float* __restrict__ a_d)
{
    int gtid = blockIdx.x * blockDim.x + threadIdx.x;
    if (gtid < 2 * HID) g_stats[gtid] = 0.f;

    int n = gtid >> 5;
    int lane = gtid & 31;
    if (n >= NNODES) return;

    float4 hv = *(const float4*)(h + (size_t)n * HID + lane * 4);
    float4 s4 = *(const float4*)(a_s + lane * 4);
    float4 d4 = *(const float4*)(a_d + lane * 4);
    float ss = hv.x * s4.x + hv.y * s4.y + hv.z * s4.z + hv.w * s4.w;
    float sd = hv.x * d4.x + hv.y * d4.y + hv.z * d4.z + hv.w * d4.w;
#pragma unroll
    for (int o = 16; o > 0; o >>= 1) {
        ss += __shfl_xor_sync(0xffffffffu, ss, o);
        sd += __shfl_xor_sync(0xffffffffu, sd, o);
    }
    if (lane == 0) {
        g_as[n] = ss;
        g_ad[n] = sd;
    }
}

// ----------------------------------------------------------------------------
// Fused segment softmax + aggregation: one warp per destination node.
// Gather-only — zero floating-point atomics.
// ----------------------------------------------------------------------------
__global__ void gat_node_kernel(const float* __restrict__ h,
                                const float* __restrict__ bias)
{
    int n = (blockIdx.x * blockDim.x + threadIdx.x) >> 5;
    int lane = threadIdx.x & 31;
    if (n >= NNODES) return;

    int beg = g_rowptr[n];
    int end = g_rowptr[n + 1];
    float adn = g_ad[n];
    float selfs = lrelu(g_as[n] + adn);

    // Pass 1: segment max (self-loop seeded)
    float m = selfs;
    for (int i = beg + lane; i < end; i += 32)
        m = fmaxf(m, lrelu(g_as[g_csrc[i]] + adn));
#pragma unroll
    for (int o = 16; o > 0; o >>= 1)
        m = fmaxf(m, __shfl_xor_sync(0xffffffffu, m, o));

    // Pass 2: exp-sum
    float sum = 0.f;
    for (int i = beg + lane; i < end; i += 32)
        sum += __expf(lrelu(g_as[g_csrc[i]] + adn) - m);
#pragma unroll
    for (int o = 16; o > 0; o >>= 1)
        sum += __shfl_xor_sync(0xffffffffu, sum, o);
    sum += __expf(selfs - m);
    float inv = __fdividef(1.f, sum);

    // Pass 3: weighted accumulate. Warp iterates edges together,
    // lanes own 4 channels each (128 total).
    float cs = __expf(selfs - m) * inv;
    float4 hv = *(const float4*)(h + (size_t)n * HID + lane * 4);
    float4 acc;
    acc.x = cs * hv.x; acc.y = cs * hv.y; acc.z = cs * hv.z; acc.w = cs * hv.w;

    for (int i = beg; i < end; i++) {
        int s = g_csrc[i];                                   // broadcast load
        float c = __expf(lrelu(g_as[s] + adn) - m) * inv;
        float4 v = *(const float4*)(h + (size_t)s * HID + lane * 4);
        acc.x += c * v.x; acc.y += c * v.y; acc.z += c * v.z; acc.w += c * v.w;
    }

    float4 bv = *(const float4*)(bias + lane * 4);
    acc.x += bv.x; acc.y += bv.y; acc.z += bv.z; acc.w += bv.w;
    *(float4*)(g_out + (size_t)n * HID + lane * 4) = acc;
}

// ----------------------------------------------------------------------------
// BN stats: block-local per-channel sum/sumsq, one global atomic per channel
// ----------------------------------------------------------------------------
__global__ void bnstats_kernel()
{
    __shared__ float ssum[HID];
    __shared__ float ssq[HID];
    int t = threadIdx.x;
    int c = t & (HID - 1);
    int half = t >> 7;               // 0 or 1 (256 threads)
    int n0 = blockIdx.x * 128;

    float sum = 0.f, sq = 0.f;
    for (int i = half; i < 128; i += 2) {
        int n = n0 + i;
        if (n < NNODES) {
            float v = g_out[(size_t)n * HID + c];
            sum += v;
            sq  += v * v;
        }
    }
    if (half == 1) { ssum[c] = sum; ssq[c] = sq; }
    __syncthreads();
    if (half == 0) {
        sum += ssum[c];
        sq  += ssq[c];
        atomicAdd(&g_stats[c], sum);
        atomicAdd(&g_stats[HID + c], sq);
    }
}

// ----------------------------------------------------------------------------
// BN apply + ReLU
// ----------------------------------------------------------------------------
__global__ void bnapply_kernel(const float* __restrict__ gamma,
                               const float* __restrict__ beta)
{
    size_t tid = (size_t)blockIdx.x * blockDim.x + threadIdx.x;
    if (tid >= (size_t)NNODES * HID) return;
    int c = (int)(tid & (HID - 1));
    float inv_n = 1.0f / (float)NNODES;
    float mean = g_stats[c] * inv_n;
    float var  = g_stats[HID + c] * inv_n - mean * mean;
    float y = (g_out[tid] - mean) * rsqrtf(var + BN_EPS) * gamma[c] + beta[c];
    g_bn[tid] = y > 0.f ? y : 0.f;
}

// ----------------------------------------------------------------------------
// Host-side orchestration
// ----------------------------------------------------------------------------
static void run_gat_layer(const float* X, const float* W, const float* a_s,
                          const float* a_d, const float* b, const float* gamma,
                          const float* beta, float* d_h)
{
    const int gemm_grid = (NNODES + 127) / 128;
    sgemm_kernel<128, 128, 16, 8, 8, false><<<gemm_grid, 256>>>(X, W, nullptr, d_h,
                                                                NNODES, FDIM, HID);
    alphadot_kernel<<<(NNODES * 32 + 255) / 256, 256>>>(d_h, a_s, a_d);
    gat_node_kernel<<<(NNODES * 32 + 255) / 256, 256>>>(d_h, b);
    bnstats_kernel<<<(NNODES + 127) / 128, 256>>>();
    bnapply_kernel<<<(NNODES * HID + 255) / 256, 256>>>(gamma, beta);
}

extern "C" void kernel_launch(void* const* d_in, const int* in_sizes, int n_in,
                              void* d_out, int out_size)
{
    const float* x    = (const float*)d_in[0];
    const int*   ei   = (const int*)d_in[1];     // int32! (JAX x64 disabled)
    const float* W1   = (const float*)d_in[2];
    const float* as1  = (const float*)d_in[3];
    const float* ad1  = (const float*)d_in[4];
    const float* b1   = (const float*)d_in[5];
    const float* g1   = (const float*)d_in[6];
    const float* be1  = (const float*)d_in[7];
    const float* W2   = (const float*)d_in[8];
    const float* as2  = (const float*)d_in[9];
    const float* ad2  = (const float*)d_in[10];
    const float* b2   = (const float*)d_in[11];
    const float* g2   = (const float*)d_in[12];
    const float* be2  = (const float*)d_in[13];
    const float* Wc   = (const float*)d_in[14];
    const float* bc   = (const float*)d_in[15];
    float*       out  = (float*)d_out;

    int E = in_sizes[1] / 2;
    if (E > EMAX) E = EMAX;
    const int* srcp = ei;
    const int* dstp = ei + E;

    float* d_h;
    cudaGetSymbolAddress((void**)&d_h, g_h);
    float* d_bn;
    cudaGetSymbolAddress((void**)&d_bn, g_bn);

    // ---- Build CSR (dst -> srcs), once per launch ----
    csr_zero_kernel<<<(NNODES + 255) / 256, 256>>>();
    csr_count_kernel<<<(E + 255) / 256, 256>>>(dstp, E);
    csr_scan_block_kernel<<<NSCANBLK, SCAN_BLK>>>();
    csr_scan_tops_kernel<<<1, 128>>>(NSCANBLK, E);
    csr_addoff_kernel<<<NSCANBLK, SCAN_BLK>>>();
    csr_fill_kernel<<<(E + 255) / 256, 256>>>(srcp, dstp, E);

    // ---- Layer 1 (input x), Layer 2 (input g_bn) ----
    run_gat_layer(x, W1, as1, ad1, b1, g1, be1, d_h);
    run_gat_layer(d_bn, W2, as2, ad2, b2, g2, be2, d_h);

    // ---- Classifier: out = g_bn @ Wc + bc ----
    const int gemm_grid = (NNODES + 127) / 128;
    sgemm_kernel<128, 64, 16, 8, 8, true><<<gemm_grid, 128>>>(d_bn, Wc, bc, out,
                                                              NNODES, HID, NCLS);
}

// round 4
// speedup vs baseline: 1.5239x; 1.5239x over previous
#include <cuda_runtime.h>
#include <cuda_bf16.h>
#include <cstdint>

// Problem constants (fixed by the reference)
#define NNODES 100000
#define FDIM   128
#define HID    128
#define NCLS   40
#define EMAX   1600000
#define NEG_SLOPE 0.2f
#define BN_EPS 1e-5f

#define SCAN_BLK 1024
#define NSCANBLK ((NNODES + SCAN_BLK - 1) / SCAN_BLK)   // 98

// ----------------------------------------------------------------------------
// Device scratch (static globals — no runtime allocation allowed)
// ----------------------------------------------------------------------------
__device__ float g_h[NNODES * HID];      // linear output of current layer
__device__ float g_out[NNODES * HID];    // GAT aggregation output / BN input
__device__ float g_bn[NNODES * HID];     // post-BN+ReLU activations
__device__ float g_as[NNODES];
__device__ float g_ad[NNODES];
__device__ float g_stats[2 * HID];       // per-channel sum / sumsq

// CSR (dst -> list of src), rebuilt every launch (deterministic)
__device__ int g_deg[NNODES];
__device__ int g_fill[NNODES];
__device__ int g_rowptr[NNODES + 1];
__device__ int g_blocksum[128];
__device__ int g_csrc[EMAX];

// ----------------------------------------------------------------------------
__device__ __forceinline__ float lrelu(float x) {
    return x > 0.f ? x : NEG_SLOPE * x;
}

__device__ __forceinline__ unsigned f2tf32(float f) {
    unsigned r;
    asm("cvt.rna.tf32.f32 %0, %1;" : "=r"(r) : "f"(f));
    return r;
}

__device__ __forceinline__ void mma_tf32(float d[4], const unsigned a[4],
                                         const unsigned b[2], const float c[4]) {
    asm volatile(
        "mma.sync.aligned.m16n8k8.row.col.f32.tf32.tf32.f32 "
        "{%0,%1,%2,%3}, {%4,%5,%6,%7}, {%8,%9}, {%10,%11,%12,%13};"
        : "=f"(d[0]), "=f"(d[1]), "=f"(d[2]), "=f"(d[3])
        : "r"(a[0]), "r"(a[1]), "r"(a[2]), "r"(a[3]),
          "r"(b[0]), "r"(b[1]),
          "f"(c[0]), "f"(c[1]), "f"(c[2]), "f"(c[3]));
}

// ----------------------------------------------------------------------------
// Tensor-core GEMM (tf32 mma.sync): C[M,NC] = A[M,K] @ B[K,NC] (+ bias)
// Block tile BM x BN, K-chunks of 16 (two k=8 mma steps).
// Warp layout: NWM x NWN warps; warp tile (BM/NWM) x (BN/NWN).
// ----------------------------------------------------------------------------
template<int BM, int BN, int NWM, int NWN, bool BIAS, bool NGUARD>
__global__ void mma_gemm_kernel(const float* __restrict__ A,
                                const float* __restrict__ B,
                                const float* __restrict__ bias,
                                float* __restrict__ C,
                                int M, int K, int NC)
{
    constexpr int BK = 16;
    constexpr int THREADS = NWM * NWN * 32;
    constexpr int WM = BM / NWM;          // warp tile rows
    constexpr int WN = BN / NWN;          // warp tile cols
    constexpr int MT = WM / 16;           // m16 tiles per warp
    constexpr int NT = WN / 8;            // n8 tiles per warp

    __shared__ unsigned As[BK][BM + 4];   // tf32 bits, k-major
    __shared__ unsigned Bs[BK][BN + 4];   // tf32 bits, k-major

    const int tid    = threadIdx.x;
    const int warpId = tid >> 5;
    const int lane   = tid & 31;
    const int warpM  = warpId % NWM;
    const int warpN  = warpId / NWM;
    const int t      = lane & 3;          // thread-in-group
    const int g      = lane >> 2;         // group id
    const int rowBase = blockIdx.x * BM;

    float acc[MT][NT][4];
#pragma unroll
    for (int i = 0; i < MT; i++)
#pragma unroll
        for (int j = 0; j < NT; j++)
#pragma unroll
            for (int r = 0; r < 4; r++) acc[i][j][r] = 0.f;

    for (int k0 = 0; k0 < K; k0 += BK) {
        // Load A tile (BM x BK) transposed into As[k][m]
#pragma unroll
        for (int i = tid; i < BM * BK; i += THREADS) {
            int m = i / BK, k = i % BK;
            int gr = rowBase + m;
            float v = (gr < M) ? A[(size_t)gr * K + k0 + k] : 0.f;
            As[k][m] = f2tf32(v);
        }
        // Load B tile (BK x BN) into Bs[k][n]
#pragma unroll
        for (int i = tid; i < BK * BN; i += THREADS) {
            int k = i / BN, n = i % BN;
            float v = (!NGUARD || n < NC) ? B[(size_t)(k0 + k) * NC + n] : 0.f;
            Bs[k][n] = f2tf32(v);
        }
        __syncthreads();

#pragma unroll
        for (int ks = 0; ks < BK; ks += 8) {
            unsigned afrag[MT][4];
#pragma unroll
            for (int mt = 0; mt < MT; mt++) {
                int mr = warpM * WM + mt * 16;
                afrag[mt][0] = As[ks + t][mr + g];
                afrag[mt][1] = As[ks + t][mr + g + 8];
                afrag[mt][2] = As[ks + t + 4][mr + g];
                afrag[mt][3] = As[ks + t + 4][mr + g + 8];
            }
            unsigned bfrag[NT][2];
#pragma unroll
            for (int nt = 0; nt < NT; nt++) {
                int nc0 = warpN * WN + nt * 8;
                bfrag[nt][0] = Bs[ks + t][nc0 + g];
                bfrag[nt][1] = Bs[ks + t + 4][nc0 + g];
            }
#pragma unroll
            for (int mt = 0; mt < MT; mt++)
#pragma unroll
                for (int nt = 0; nt < NT; nt++)
                    mma_tf32(acc[mt][nt], afrag[mt], bfrag[nt], acc[mt][nt]);
        }
        __syncthreads();
    }

    // Epilogue: c0,c1 = (row g, cols 2t,2t+1); c2,c3 = (row g+8)
#pragma unroll
    for (int mt = 0; mt < MT; mt++) {
#pragma unroll
        for (int nt = 0; nt < NT; nt++) {
            int col = warpN * WN + nt * 8 + 2 * t;
            if (NGUARD && col >= NC) continue;
            float b0 = 0.f, b1 = 0.f;
            if (BIAS) { b0 = bias[col]; b1 = bias[col + 1]; }
            int row0 = rowBase + warpM * WM + mt * 16 + g;
            if (row0 < M) {
                float2 v = make_float2(acc[mt][nt][0] + b0, acc[mt][nt][1] + b1);
                *(float2*)(C + (size_t)row0 * NC + col) = v;
            }
            int row1 = row0 + 8;
            if (row1 < M) {
                float2 v = make_float2(acc[mt][nt][2] + b0, acc[mt][nt][3] + b1);
                *(float2*)(C + (size_t)row1 * NC + col) = v;
            }
        }
    }
}

// ----------------------------------------------------------------------------
// CSR build kernels (edge indices are int32 — JAX x64 is disabled by default)
// ----------------------------------------------------------------------------
__global__ void csr_zero_kernel()
{
    int i = blockIdx.x * blockDim.x + threadIdx.x;
    if (i < NNODES) { g_deg[i] = 0; g_fill[i] = 0; }
}

__global__ void csr_count_kernel(const int* __restrict__ dstp, int E)
{
    int e = blockIdx.x * blockDim.x + threadIdx.x;
    if (e < E) atomicAdd(&g_deg[dstp[e]], 1);
}

__global__ void csr_scan_block_kernel()
{
    __shared__ int s[SCAN_BLK];
    int t = threadIdx.x;
    int i = blockIdx.x * SCAN_BLK + t;
    int v = (i < NNODES) ? g_deg[i] : 0;
    s[t] = v;
    __syncthreads();
#pragma unroll
    for (int off = 1; off < SCAN_BLK; off <<= 1) {
        int x = (t >= off) ? s[t - off] : 0;
        __syncthreads();
        s[t] += x;
        __syncthreads();
    }
    if (i < NNODES) g_rowptr[i] = s[t] - v;       // exclusive within block
    if (t == SCAN_BLK - 1) g_blocksum[blockIdx.x] = s[t];
}

__global__ void csr_scan_tops_kernel(int nblocks, int E)
{
    __shared__ int s[128];
    int t = threadIdx.x;                            // 128 threads
    int v = (t < nblocks) ? g_blocksum[t] : 0;
    s[t] = v;
    __syncthreads();
#pragma unroll
    for (int off = 1; off < 128; off <<= 1) {
        int x = (t >= off) ? s[t - off] : 0;
        __syncthreads();
        s[t] += x;
        __syncthreads();
    }
    g_blocksum[t] = s[t] - v;                       // exclusive block offsets
    if (t == 0) g_rowptr[NNODES] = E;
}

__global__ void csr_addoff_kernel()
{
    int i = blockIdx.x * SCAN_BLK + threadIdx.x;
    if (i < NNODES) g_rowptr[i] += g_blocksum[blockIdx.x];
}

__global__ void csr_fill_kernel(const int* __restrict__ srcp,
                                const int* __restrict__ dstp, int E)
{
    int e = blockIdx.x * blockDim.x + threadIdx.x;
    if (e >= E) return;
    int d = dstp[e];
    int p = atomicAdd(&g_fill[d], 1);
    g_csrc[g_rowptr[d] + p] = srcp[e];
}

// ----------------------------------------------------------------------------
// Per-node attention dots (warp per node) + zero BN stats
// ----------------------------------------------------------------------------
__global__ void alphadot_kernel(const float* __restrict__ h,
                                const float* __restrict__ a_s,
                                const float* __restrict__ a_d)
{
    int gtid = blockIdx.x * blockDim.x + threadIdx.x;
    if (gtid < 2 * HID) g_stats[gtid] = 0.f;

    int n = gtid >> 5;
    int lane = gtid & 31;
    if (n >= NNODES) return;

    float4 hv = *(const float4*)(h + (size_t)n * HID + lane * 4);
    float4 s4 = *(const float4*)(a_s + lane * 4);
    float4 d4 = *(const float4*)(a_d + lane * 4);
    float ss = hv.x * s4.x + hv.y * s4.y + hv.z * s4.z + hv.w * s4.w;
    float sd = hv.x * d4.x + hv.y * d4.y + hv.z * d4.z + hv.w * d4.w;
#pragma unroll
    for (int o = 16; o > 0; o >>= 1) {
        ss += __shfl_xor_sync(0xffffffffu, ss, o);
        sd += __shfl_xor_sync(0xffffffffu, sd, o);
    }
    if (lane == 0) {
        g_as[n] = ss;
        g_ad[n] = sd;
    }
}

// ----------------------------------------------------------------------------
// Fused segment softmax + aggregation: one warp per destination node.
// Gather-only — zero floating-point atomics.
// ----------------------------------------------------------------------------
__global__ void gat_node_kernel(const float* __restrict__ h,
                                const float* __restrict__ bias)
{
    int n = (blockIdx.x * blockDim.x + threadIdx.x) >> 5;
    int lane = threadIdx.x & 31;
    if (n >= NNODES) return;

    int beg = g_rowptr[n];
    int end = g_rowptr[n + 1];
    float adn = g_ad[n];
    float selfs = lrelu(g_as[n] + adn);

    // Pass 1: segment max (self-loop seeded)
    float m = selfs;
    for (int i = beg + lane; i < end; i += 32)
        m = fmaxf(m, lrelu(g_as[g_csrc[i]] + adn));
#pragma unroll
    for (int o = 16; o > 0; o >>= 1)
        m = fmaxf(m, __shfl_xor_sync(0xffffffffu, m, o));

    // Pass 2: exp-sum
    float sum = 0.f;
    for (int i = beg + lane; i < end; i += 32)
        sum += __expf(lrelu(g_as[g_csrc[i]] + adn) - m);
#pragma unroll
    for (int o = 16; o > 0; o >>= 1)
        sum += __shfl_xor_sync(0xffffffffu, sum, o);
    sum += __expf(selfs - m);
    float inv = __fdividef(1.f, sum);

    // Pass 3: weighted accumulate. Warp iterates edges together,
    // lanes own 4 channels each (128 total).
    float cs = __expf(selfs - m) * inv;
    float4 hv = *(const float4*)(h + (size_t)n * HID + lane * 4);
    float4 acc;
    acc.x = cs * hv.x; acc.y = cs * hv.y; acc.z = cs * hv.z; acc.w = cs * hv.w;

    for (int i = beg; i < end; i++) {
        int s = g_csrc[i];                                   // broadcast load
        float c = __expf(lrelu(g_as[s] + adn) - m) * inv;
        float4 v = *(const float4*)(h + (size_t)s * HID + lane * 4);
        acc.x += c * v.x; acc.y += c * v.y; acc.z += c * v.z; acc.w += c * v.w;
    }

    float4 bv = *(const float4*)(bias + lane * 4);
    acc.x += bv.x; acc.y += bv.y; acc.z += bv.z; acc.w += bv.w;
    *(float4*)(g_out + (size_t)n * HID + lane * 4) = acc;
}

// ----------------------------------------------------------------------------
// BN stats: block-local per-channel sum/sumsq, one global atomic per channel
// ----------------------------------------------------------------------------
__global__ void bnstats_kernel()
{
    __shared__ float ssum[HID];
    __shared__ float ssq[HID];
    int t = threadIdx.x;
    int c = t & (HID - 1);
    int half = t >> 7;               // 0 or 1 (256 threads)
    int n0 = blockIdx.x * 128;

    float sum = 0.f, sq = 0.f;
    for (int i = half; i < 128; i += 2) {
        int n = n0 + i;
        if (n < NNODES) {
            float v = g_out[(size_t)n * HID + c];
            sum += v;
            sq  += v * v;
        }
    }
    if (half == 1) { ssum[c] = sum; ssq[c] = sq; }
    __syncthreads();
    if (half == 0) {
        sum += ssum[c];
        sq  += ssq[c];
        atomicAdd(&g_stats[c], sum);
        atomicAdd(&g_stats[HID + c], sq);
    }
}

// ----------------------------------------------------------------------------
// BN apply + ReLU
// ----------------------------------------------------------------------------
__global__ void bnapply_kernel(const float* __restrict__ gamma,
                               const float* __restrict__ beta)
{
    size_t tid = (size_t)blockIdx.x * blockDim.x + threadIdx.x;
    if (tid >= (size_t)NNODES * HID) return;
    int c = (int)(tid & (HID - 1));
    float inv_n = 1.0f / (float)NNODES;
    float mean = g_stats[c] * inv_n;
    float var  = g_stats[HID + c] * inv_n - mean * mean;
    float y = (g_out[tid] - mean) * rsqrtf(var + BN_EPS) * gamma[c] + beta[c];
    g_bn[tid] = y > 0.f ? y : 0.f;
}

// ----------------------------------------------------------------------------
// Host-side orchestration
// ----------------------------------------------------------------------------
static void run_gat_layer(const float* X, const float* W, const float* a_s,
                          const float* a_d, const float* b, const float* gamma,
                          const float* beta, float* d_h)
{
    const int gemm_grid = (NNODES + 127) / 128;
    mma_gemm_kernel<128, 128, 4, 2, false, false><<<gemm_grid, 256>>>(
        X, W, nullptr, d_h, NNODES, FDIM, HID);
    alphadot_kernel<<<(NNODES * 32 + 255) / 256, 256>>>(d_h, a_s, a_d);
    gat_node_kernel<<<(NNODES * 32 + 255) / 256, 256>>>(d_h, b);
    bnstats_kernel<<<(NNODES + 127) / 128, 256>>>();
    bnapply_kernel<<<(NNODES * HID + 255) / 256, 256>>>(gamma, beta);
}

extern "C" void kernel_launch(void* const* d_in, const int* in_sizes, int n_in,
                              void* d_out, int out_size)
{
    const float* x    = (const float*)d_in[0];
    const int*   ei   = (const int*)d_in[1];     // int32! (JAX x64 disabled)
    const float* W1   = (const float*)d_in[2];
    const float* as1  = (const float*)d_in[3];
    const float* ad1  = (const float*)d_in[4];
    const float* b1   = (const float*)d_in[5];
    const float* g1   = (const float*)d_in[6];
    const float* be1  = (const float*)d_in[7];
    const float* W2   = (const float*)d_in[8];
    const float* as2  = (const float*)d_in[9];
    const float* ad2  = (const float*)d_in[10];
    const float* b2   = (const float*)d_in[11];
    const float* g2   = (const float*)d_in[12];
    const float* be2  = (const float*)d_in[13];
    const float* Wc   = (const float*)d_in[14];
    const float* bc   = (const float*)d_in[15];
    float*       out  = (float*)d_out;

    int E = in_sizes[1] / 2;
    if (E > EMAX) E = EMAX;
    const int* srcp = ei;
    const int* dstp = ei + E;

    float* d_h;
    cudaGetSymbolAddress((void**)&d_h, g_h);
    float* d_bn;
    cudaGetSymbolAddress((void**)&d_bn, g_bn);

    // ---- Build CSR (dst -> srcs), once per launch ----
    csr_zero_kernel<<<(NNODES + 255) / 256, 256>>>();
    csr_count_kernel<<<(E + 255) / 256, 256>>>(dstp, E);
    csr_scan_block_kernel<<<NSCANBLK, SCAN_BLK>>>();
    csr_scan_tops_kernel<<<1, 128>>>(NSCANBLK, E);
    csr_addoff_kernel<<<NSCANBLK, SCAN_BLK>>>();
    csr_fill_kernel<<<(E + 255) / 256, 256>>>(srcp, dstp, E);

    // ---- Layer 1 (input x), Layer 2 (input g_bn) ----
    run_gat_layer(x, W1, as1, ad1, b1, g1, be1, d_h);
    run_gat_layer(d_bn, W2, as2, ad2, b2, g2, be2, d_h);

    // ---- Classifier: out = g_bn @ Wc + bc ----
    const int gemm_grid = (NNODES + 127) / 128;
    mma_gemm_kernel<128, 64, 4, 2, true, true><<<gemm_grid, 256>>>(
        d_bn, Wc, bc, out, NNODES, HID, NCLS);
}